// round 15
// baseline (speedup 1.0000x reference)
#include <cuda_runtime.h>
#include <math.h>

#define B_ 4
#define S_ 2048
#define D_ 1024
#define H_ 16
#define DH_ 64
#define E_ 8
#define DFF_ 4096
#define T_ (B_*S_)          // 8192 tokens

// ---------------- scratch (device globals; no cudaMalloc allowed) ----------
__device__ float g_hh[(size_t)T_*D_];           // LN1 out, tf32 hi plane
__device__ float g_hl[(size_t)T_*D_];           // LN1 out, tf32 lo plane
__device__ float g_qkv[(size_t)T_*3*D_];        // qkv
__device__ float g_ah[(size_t)T_*D_];           // attention out, hi plane
__device__ float g_al[(size_t)T_*D_];           // attention out, lo plane
__device__ float g_x1[(size_t)T_*D_];           // post-attn residual
__device__ float g_moeinR[(size_t)T_*D_];       // LN2 out, RNA tf32 (GEMM1 A)
__device__ float g_he[(size_t)2*T_*DFF_];       // expert hidden (rounded)
__device__ float g_ybuf[(size_t)2*T_*D_];       // expert out
__device__ int   g_cnt[E_];
__device__ int   g_exTok[E_*T_];
__device__ int   g_exDst[E_*T_];
__device__ float g_tokW[2*T_];

// smem geometry
#define AS_SZ (128*36)
#define BS_SZ (32*136)
#define STG_SZ (AS_SZ + BS_SZ)
#define DSMEM_BYTES (2*STG_SZ*4)            // 71680 B (MoE, 2-stage)
#define STG3_SZ (2*AS_SZ + BS_SZ)
#define MMA3_SMEM (2*STG3_SZ*4)             // 108544 B (2 CTAs/SM)
#define ATTN_SMEM (2*64*68*8 + 8192*4)      // 102400 B (2 CTAs/SM)

__device__ __forceinline__ unsigned f2tf32(float x) {
    unsigned r;
    asm("cvt.rna.tf32.f32 %0, %1;" : "=r"(r) : "f"(x));
    return r;
}
__device__ __forceinline__ float rndtf32(float x) {
    return __uint_as_float(f2tf32(x));
}
__device__ __forceinline__ float gelu_fast(float u) {
    // gelu tanh-approx with fast tanh: tanh(t) = sign(t)*(1-e)/(1+e), e = exp(-2|t|)
    float t = 0.7978845608028654f*(u + 0.044715f*u*u*u);
    float a = fabsf(t);
    float e = __expf(-2.f*a);
    float th = __fdividef(1.f - e, 1.f + e);
    th = copysignf(th, t);
    return 0.5f*u*(1.f + th);
}
__device__ __forceinline__ void cpasync16(float* dst, const float* src, bool pred) {
    unsigned d = (unsigned)__cvta_generic_to_shared(dst);
    int sz = pred ? 16 : 0;
    asm volatile("cp.async.cg.shared.global [%0], [%1], 16, %2;\n"
                 :: "r"(d), "l"(src), "r"(sz));
}
#define MMA_TF32(c, a0,a1,a2,a3, b0,b1)                                     \
    asm volatile(                                                           \
        "mma.sync.aligned.m16n8k8.row.col.f32.tf32.tf32.f32 "               \
        "{%0,%1,%2,%3}, {%4,%5,%6,%7}, {%8,%9}, {%0,%1,%2,%3};\n"           \
        : "+f"((c)[0]), "+f"((c)[1]), "+f"((c)[2]), "+f"((c)[3])            \
        : "r"(a0), "r"(a1), "r"(a2), "r"(a3), "r"(b0), "r"(b1))

// ---------------------------------------------------------------- zero cnt
__global__ void zero_cnt_kernel() {
    if (threadIdx.x < E_) g_cnt[threadIdx.x] = 0;
}

// ---------------------------------------------------------------- LN2 + gate fused
// Computes layernorm (fp32 in regs), gate logits + top2 routing, and writes
// ONLY the RNA-rounded plane for GEMM1.
__global__ void ln2_gate_kernel(const float* __restrict__ x,
                                const float* __restrict__ g,
                                const float* __restrict__ b,
                                const float* __restrict__ wg,
                                float* __restrict__ outR) {
    int row = blockIdx.x;
    int t = threadIdx.x;                 // 256
    const float* xr = x + (size_t)row * D_;
    float4 v = *(const float4*)(xr + t*4);
    float s = v.x + v.y + v.z + v.w;
    float ss = v.x*v.x + v.y*v.y + v.z*v.z + v.w*v.w;
#pragma unroll
    for (int m = 16; m; m >>= 1) {
        s  += __shfl_xor_sync(~0u, s, m);
        ss += __shfl_xor_sync(~0u, ss, m);
    }
    __shared__ float rs[8], rss[8];
    if ((t & 31) == 0) { rs[t>>5] = s; rss[t>>5] = ss; }
    __syncthreads();
    float sum = 0.f, sumsq = 0.f;
#pragma unroll
    for (int i = 0; i < 8; i++) { sum += rs[i]; sumsq += rss[i]; }
    float mean = sum * (1.f/D_);
    float var  = sumsq * (1.f/D_) - mean*mean;
    float rstd = rsqrtf(var + 1e-5f);
    float4 gv = *(const float4*)(g + t*4);
    float4 bv = *(const float4*)(b + t*4);
    float o[4];
    o[0] = (v.x-mean)*rstd*gv.x + bv.x;
    o[1] = (v.y-mean)*rstd*gv.y + bv.y;
    o[2] = (v.z-mean)*rstd*gv.z + bv.z;
    o[3] = (v.w-mean)*rstd*gv.w + bv.w;

    // rounded plane for the MoE GEMM
    float4 oR;
    oR.x = rndtf32(o[0]); oR.y = rndtf32(o[1]);
    oR.z = rndtf32(o[2]); oR.w = rndtf32(o[3]);
    *(float4*)(outR + (size_t)row * D_ + t*4) = oR;

    // gate logits (fp32, unrounded values)
    float acc[E_] = {};
#pragma unroll
    for (int i = 0; i < 4; i++) {
        const float* w = wg + (size_t)(t*4 + i)*E_;
#pragma unroll
        for (int e = 0; e < E_; e++) acc[e] = fmaf(o[i], w[e], acc[e]);
    }
#pragma unroll
    for (int e = 0; e < E_; e++)
#pragma unroll
        for (int msk = 16; msk; msk >>= 1)
            acc[e] += __shfl_xor_sync(~0u, acc[e], msk);
    __shared__ float red[8][E_];
    if ((t & 31) == 0)
#pragma unroll
        for (int e = 0; e < E_; e++) red[t>>5][e] = acc[e];
    __syncthreads();
    if (t == 0) {
        float lg[E_];
#pragma unroll
        for (int e = 0; e < E_; e++) {
            float q = 0.f;
#pragma unroll
            for (int w = 0; w < 8; w++) q += red[w][e];
            lg[e] = q;
        }
        int i0 = 0;
#pragma unroll
        for (int e = 1; e < E_; e++) if (lg[e] > lg[i0]) i0 = e;
        int i1 = -1;
#pragma unroll
        for (int e = 0; e < E_; e++)
            if (e != i0 && (i1 < 0 || lg[e] > lg[i1])) i1 = e;
        float d10 = __expf(lg[i1] - lg[i0]);
        float w0 = 1.f / (1.f + d10);
        float w1 = d10 * w0;
        g_tokW[2*row]   = w0;
        g_tokW[2*row+1] = w1;
        int p0 = atomicAdd(&g_cnt[i0], 1);
        g_exTok[i0*T_ + p0] = row;  g_exDst[i0*T_ + p0] = 2*row;
        int p1 = atomicAdd(&g_cnt[i1], 1);
        g_exTok[i1*T_ + p1] = row;  g_exDst[i1*T_ + p1] = 2*row+1;
    }
}

// ---------------------------------------------------------------- layernorm (hi/lo split out)
__global__ void ln_split_kernel(const float* __restrict__ x,
                                const float* __restrict__ g,
                                const float* __restrict__ b,
                                float* __restrict__ outh,
                                float* __restrict__ outl) {
    int row = blockIdx.x;
    int t = threadIdx.x;
    const float* xr = x + (size_t)row * D_;
    float4 v = *(const float4*)(xr + t*4);
    float s = v.x + v.y + v.z + v.w;
    float ss = v.x*v.x + v.y*v.y + v.z*v.z + v.w*v.w;
#pragma unroll
    for (int m = 16; m; m >>= 1) {
        s  += __shfl_xor_sync(~0u, s, m);
        ss += __shfl_xor_sync(~0u, ss, m);
    }
    __shared__ float rs[8], rss[8];
    if ((t & 31) == 0) { rs[t>>5] = s; rss[t>>5] = ss; }
    __syncthreads();
    float sum = 0.f, sumsq = 0.f;
#pragma unroll
    for (int i = 0; i < 8; i++) { sum += rs[i]; sumsq += rss[i]; }
    float mean = sum * (1.f/D_);
    float var  = sumsq * (1.f/D_) - mean*mean;
    float rstd = rsqrtf(var + 1e-5f);
    float4 gv = *(const float4*)(g + t*4);
    float4 bv = *(const float4*)(b + t*4);
    float vv[4] = {v.x, v.y, v.z, v.w};
    float gg[4] = {gv.x, gv.y, gv.z, gv.w};
    float bb[4] = {bv.x, bv.y, bv.z, bv.w};
    float4 oh, ol;
    float* ohp = &oh.x; float* olp = &ol.x;
#pragma unroll
    for (int i = 0; i < 4; i++) {
        float h = (vv[i]-mean)*rstd*gg[i] + bb[i];
        float hf = rndtf32(h);
        ohp[i] = hf;
        olp[i] = rndtf32(h - hf);
    }
    *(float4*)(outh + (size_t)row * D_ + t*4) = oh;
    *(float4*)(outl + (size_t)row * D_ + t*4) = ol;
}

// ---------------------------------------------------------------- MoE mma (2-stage)
template<bool GELU>
__global__ void __launch_bounds__(256, 2)
moe_mma_kernel(const float* __restrict__ A,
               const float* __restrict__ Bw,
               const float* __restrict__ bias,
               float* __restrict__ C,
               int N, int K,
               const int* __restrict__ gatherA,
               const int* __restrict__ scatterC,
               const int* __restrict__ cnt,
               size_t bStride, int biasStride, int listStride)
{
    extern __shared__ float smem[];
    int e = blockIdx.z;
    int Me = cnt[e];
    int m0 = blockIdx.y * 128;
    if (m0 >= Me) return;
    int n0 = blockIdx.x * 128;

    const float* Bp    = Bw + (size_t)e * bStride;
    const float* biasp = bias + (size_t)e * biasStride;
    const int*   gA    = gatherA  + (size_t)e * listStride;
    const int*   sC    = scatterC + (size_t)e * listStride;

    int tid = threadIdx.x, lane = tid & 31, warp = tid >> 5;
    int wm = warp >> 2, wn = warp & 3;
    int fr = lane >> 2, fc = lane & 3;

    int aRowBase = tid >> 3;
    int aKq = (tid & 7) * 4;
    const float* aSrc[4]; bool aValid[4];
#pragma unroll
    for (int i = 0; i < 4; i++) {
        int r = aRowBase + i*32;
        int rowA = m0 + r;
        aValid[i] = rowA < Me;
        aSrc[i] = aValid[i] ? (A + (size_t)gA[rowA]*K + aKq) : A;
    }
    int bKBase = tid >> 5;
    int bn4 = (tid & 31) * 4;
    const float* bSrc[4];
#pragma unroll
    for (int i = 0; i < 4; i++)
        bSrc[i] = Bp + (size_t)(bKBase + i*8)*N + n0 + bn4;

    float acc[4][4][4];
#pragma unroll
    for (int mi = 0; mi < 4; mi++)
#pragma unroll
        for (int ni = 0; ni < 4; ni++)
#pragma unroll
            for (int j = 0; j < 4; j++) acc[mi][ni][j] = 0.f;

    int nk = K >> 5;

    auto prefetch = [&](int s, int kt) {
        float* As_ = smem + s*STG_SZ;
        float* Bs_ = As_ + AS_SZ;
#pragma unroll
        for (int i = 0; i < 4; i++)
            cpasync16(As_ + (aRowBase + i*32)*36 + aKq,
                      aSrc[i] + (size_t)kt*32, aValid[i]);
#pragma unroll
        for (int i = 0; i < 4; i++)
            cpasync16(Bs_ + (bKBase + i*8)*136 + bn4,
                      bSrc[i] + (size_t)kt*32*N, true);
        asm volatile("cp.async.commit_group;\n");
    };

    prefetch(0, 0);

    for (int kt = 0; kt < nk; kt++) {
        int s = kt & 1;
        bool more = (kt + 1) < nk;
        if (more) prefetch(s ^ 1, kt + 1);
        if (more) asm volatile("cp.async.wait_group 1;\n");
        else      asm volatile("cp.async.wait_group 0;\n");
        __syncthreads();

        const float* As_ = smem + s*STG_SZ;
        const float* Bs_ = As_ + AS_SZ;
#pragma unroll
        for (int kk8 = 0; kk8 < 4; kk8++) {
            int kk = kk8 * 8;
            unsigned af[4][4], bf[4][2];
#pragma unroll
            for (int mi = 0; mi < 4; mi++) {
                int mb = wm*64 + mi*16;
                af[mi][0] = __float_as_uint(As_[(mb + fr    )*36 + kk + fc    ]);
                af[mi][1] = __float_as_uint(As_[(mb + fr + 8)*36 + kk + fc    ]);
                af[mi][2] = __float_as_uint(As_[(mb + fr    )*36 + kk + fc + 4]);
                af[mi][3] = __float_as_uint(As_[(mb + fr + 8)*36 + kk + fc + 4]);
            }
#pragma unroll
            for (int ni = 0; ni < 4; ni++) {
                int cb = wn*32 + ni*8;
                bf[ni][0] = f2tf32(Bs_[(kk + fc    )*136 + cb + fr]);
                bf[ni][1] = f2tf32(Bs_[(kk + fc + 4)*136 + cb + fr]);
            }
#pragma unroll
            for (int mi = 0; mi < 4; mi++)
#pragma unroll
                for (int ni = 0; ni < 4; ni++)
                    MMA_TF32(acc[mi][ni], af[mi][0],af[mi][1],af[mi][2],af[mi][3],
                             bf[ni][0], bf[ni][1]);
        }
        __syncthreads();
    }

#pragma unroll
    for (int mi = 0; mi < 4; mi++) {
        int rbase = m0 + wm*64 + mi*16 + fr;
#pragma unroll
        for (int half = 0; half < 2; half++) {
            int m = rbase + half*8;
            if (m >= Me) continue;
            int crow = sC[m];
#pragma unroll
            for (int ni = 0; ni < 4; ni++) {
                int n = n0 + wn*32 + ni*8 + fc*2;
                float v0 = acc[mi][ni][half*2 + 0] + biasp[n];
                float v1 = acc[mi][ni][half*2 + 1] + biasp[n+1];
                if (GELU) {
                    v0 = rndtf32(gelu_fast(v0));
                    v1 = rndtf32(gelu_fast(v1));
                }
                *(float2*)(C + (size_t)crow * N + n) = make_float2(v0, v1);
            }
        }
    }
}

// ---------------------------------------------------------------- 3xTF32 dense GEMM (R10)
template<bool RES>
__global__ void __launch_bounds__(256, 2)
mma3_kernel(const float* __restrict__ Ah,
            const float* __restrict__ Al,
            const float* __restrict__ Bw,
            const float* __restrict__ bias,
            const float* __restrict__ res,
            float* __restrict__ C,
            int N, int K)
{
    extern __shared__ float smem[];
    int m0 = blockIdx.y * 128;
    int n0 = blockIdx.x * 128;

    int tid = threadIdx.x, lane = tid & 31, warp = tid >> 5;
    int wm = warp >> 2, wn = warp & 3;
    int fr = lane >> 2, fc = lane & 3;

    int aRowBase = tid >> 3;
    int aKq = (tid & 7) * 4;
    const float* ahSrc[4];
    const float* alSrc[4];
#pragma unroll
    for (int i = 0; i < 4; i++) {
        size_t off = (size_t)(m0 + aRowBase + i*32)*K + aKq;
        ahSrc[i] = Ah + off;
        alSrc[i] = Al + off;
    }
    int bKBase = tid >> 5;
    int bn4 = (tid & 31) * 4;
    const float* bSrc[4];
#pragma unroll
    for (int i = 0; i < 4; i++)
        bSrc[i] = Bw + (size_t)(bKBase + i*8)*N + n0 + bn4;

    float acc[4][4][4];
#pragma unroll
    for (int mi = 0; mi < 4; mi++)
#pragma unroll
        for (int ni = 0; ni < 4; ni++)
#pragma unroll
            for (int j = 0; j < 4; j++) acc[mi][ni][j] = 0.f;

    int nk = K >> 5;

    auto prefetch = [&](int s, int kt) {
        float* Ah_ = smem + s*STG3_SZ;
        float* Al_ = Ah_ + AS_SZ;
        float* Bs_ = Al_ + AS_SZ;
#pragma unroll
        for (int i = 0; i < 4; i++) {
            int off = (aRowBase + i*32)*36 + aKq;
            cpasync16(Ah_ + off, ahSrc[i] + (size_t)kt*32, true);
            cpasync16(Al_ + off, alSrc[i] + (size_t)kt*32, true);
        }
#pragma unroll
        for (int i = 0; i < 4; i++)
            cpasync16(Bs_ + (bKBase + i*8)*136 + bn4,
                      bSrc[i] + (size_t)kt*32*N, true);
        asm volatile("cp.async.commit_group;\n");
    };

    prefetch(0, 0);

    for (int kt = 0; kt < nk; kt++) {
        int s = kt & 1;
        bool more = (kt + 1) < nk;
        if (more) prefetch(s ^ 1, kt + 1);
        if (more) asm volatile("cp.async.wait_group 1;\n");
        else      asm volatile("cp.async.wait_group 0;\n");
        __syncthreads();

        const float* Ah_ = smem + s*STG3_SZ;
        const float* Al_ = Ah_ + AS_SZ;
        const float* Bs_ = Al_ + AS_SZ;
#pragma unroll
        for (int kk8 = 0; kk8 < 4; kk8++) {
            int kk = kk8 * 8;
            unsigned ah[4][4], al[4][4], bh[4][2], bl[4][2];
#pragma unroll
            for (int mi = 0; mi < 4; mi++) {
                int mb = wm*64 + mi*16;
                int o0 = (mb + fr    )*36 + kk + fc;
                int o1 = (mb + fr + 8)*36 + kk + fc;
                ah[mi][0] = __float_as_uint(Ah_[o0]);
                ah[mi][1] = __float_as_uint(Ah_[o1]);
                ah[mi][2] = __float_as_uint(Ah_[o0 + 4]);
                ah[mi][3] = __float_as_uint(Ah_[o1 + 4]);
                al[mi][0] = __float_as_uint(Al_[o0]);
                al[mi][1] = __float_as_uint(Al_[o1]);
                al[mi][2] = __float_as_uint(Al_[o0 + 4]);
                al[mi][3] = __float_as_uint(Al_[o1 + 4]);
            }
#pragma unroll
            for (int ni = 0; ni < 4; ni++) {
                int cb = wn*32 + ni*8;
                float u0 = Bs_[(kk + fc    )*136 + cb + fr];
                float u1 = Bs_[(kk + fc + 4)*136 + cb + fr];
                bh[ni][0] = f2tf32(u0); bl[ni][0] = f2tf32(u0 - __uint_as_float(bh[ni][0]));
                bh[ni][1] = f2tf32(u1); bl[ni][1] = f2tf32(u1 - __uint_as_float(bh[ni][1]));
            }
            // pass 1: hi*lo
#pragma unroll
            for (int mi = 0; mi < 4; mi++)
#pragma unroll
                for (int ni = 0; ni < 4; ni++)
                    MMA_TF32(acc[mi][ni], ah[mi][0],ah[mi][1],ah[mi][2],ah[mi][3],
                             bl[ni][0], bl[ni][1]);
            // pass 2: lo*hi
#pragma unroll
            for (int mi = 0; mi < 4; mi++)
#pragma unroll
                for (int ni = 0; ni < 4; ni++)
                    MMA_TF32(acc[mi][ni], al[mi][0],al[mi][1],al[mi][2],al[mi][3],
                             bh[ni][0], bh[ni][1]);
            // pass 3: hi*hi
#pragma unroll
            for (int mi = 0; mi < 4; mi++)
#pragma unroll
                for (int ni = 0; ni < 4; ni++)
                    MMA_TF32(acc[mi][ni], ah[mi][0],ah[mi][1],ah[mi][2],ah[mi][3],
                             bh[ni][0], bh[ni][1]);
        }
        __syncthreads();
    }

#pragma unroll
    for (int mi = 0; mi < 4; mi++) {
        int rbase = m0 + wm*64 + mi*16 + fr;
#pragma unroll
        for (int half = 0; half < 2; half++) {
            int m = rbase + half*8;
#pragma unroll
            for (int ni = 0; ni < 4; ni++) {
                int n = n0 + wn*32 + ni*8 + fc*2;
                float v0 = acc[mi][ni][half*2 + 0] + bias[n];
                float v1 = acc[mi][ni][half*2 + 1] + bias[n+1];
                if (RES) {
                    v0 += res[(size_t)m * N + n];
                    v1 += res[(size_t)m * N + n + 1];
                }
                *(float2*)(C + (size_t)m * N + n) = make_float2(v0, v1);
            }
        }
    }
}

// ---------------------------------------------------------------- attention (tf32x3 flash, R10)
__global__ void __launch_bounds__(128, 2)
attn_mma_kernel(const float* __restrict__ qkv,
                float* __restrict__ oh, float* __restrict__ ol)
{
    extern __shared__ float2 sm2[];
    float2* KT2 = sm2;
    float2* V2  = sm2 + 64*68;
    float*  raw = (float*)(sm2 + 2*64*68);

    int qt = blockIdx.x, h = blockIdx.y, b = blockIdx.z;
    int tid = threadIdx.x;
    int lane = tid & 31, warp = tid >> 5;
    int fr = lane >> 2, fc = lane & 3;
    int w16 = warp * 16;
    size_t base = (size_t)b * S_ * (3*D_) + h*DH_;

    auto prefetch_raw = [&](int kt) {
#pragma unroll
        for (int rep = 0; rep < 8; rep++) {
            int c = rep*128 + tid;
            int r = c >> 4, off = (c & 15) * 4;
            const float* src = qkv + base + (size_t)(kt*64 + r)*(3*D_) + D_ + off;
            cpasync16(raw + r*64 + off, src, true);
        }
#pragma unroll
        for (int rep = 0; rep < 8; rep++) {
            int c = rep*128 + tid;
            int r = c >> 4, off = (c & 15) * 4;
            const float* src = qkv + base + (size_t)(kt*64 + r)*(3*D_) + 2*D_ + off;
            cpasync16(raw + 4096 + r*64 + off, src, true);
        }
        asm volatile("cp.async.commit_group;\n");
    };
    prefetch_raw(0);

    float* Qs = (float*)V2;
#pragma unroll
    for (int rep = 0; rep < 8; rep++) {
        int lin = rep*512 + tid*4;
        int r = lin >> 6, d0 = lin & 63;
        float4 q = *(const float4*)(qkv + base + (size_t)(qt*64 + r)*(3*D_) + d0);
        Qs[r*68 + d0 + 0] = q.x * 0.125f;
        Qs[r*68 + d0 + 1] = q.y * 0.125f;
        Qs[r*68 + d0 + 2] = q.z * 0.125f;
        Qs[r*68 + d0 + 3] = q.w * 0.125f;
    }
    __syncthreads();

    unsigned qh[8][4], ql[8][4];
#pragma unroll
    for (int kt = 0; kt < 8; kt++) {
        int c0 = kt*8 + fc;
        float v[4];
        v[0] = Qs[(w16+fr  )*68 + c0];
        v[1] = Qs[(w16+fr+8)*68 + c0];
        v[2] = Qs[(w16+fr  )*68 + c0 + 4];
        v[3] = Qs[(w16+fr+8)*68 + c0 + 4];
#pragma unroll
        for (int j = 0; j < 4; j++) {
            qh[kt][j] = f2tf32(v[j]);
            ql[kt][j] = f2tf32(v[j] - __uint_as_float(qh[kt][j]));
        }
    }

    float m0 = -1e30f, m1 = -1e30f, l0 = 0.f, l1 = 0.f;
    float oacc[8][4];
#pragma unroll
    for (int nt = 0; nt < 8; nt++)
#pragma unroll
        for (int j = 0; j < 4; j++) oacc[nt][j] = 0.f;

    for (int ktile = 0; ktile < S_/64; ktile++) {
        asm volatile("cp.async.wait_group 0;\n");
        __syncthreads();

#pragma unroll
        for (int rep = 0; rep < 8; rep++) {
            int lin = rep*512 + tid*4;
            int r = lin >> 6, d0 = lin & 63;
            float4 kv = *(const float4*)(raw + r*64 + d0);
            float kva[4] = {kv.x, kv.y, kv.z, kv.w};
#pragma unroll
            for (int i = 0; i < 4; i++) {
                int d = d0 + i;
                float hf = rndtf32(kva[i]);
                int col = r ^ ((d >> 2) & 15);
                KT2[d*68 + col] = make_float2(hf, kva[i] - hf);
            }
            float4 vv = *(const float4*)(raw + 4096 + r*64 + d0);
            float vva[4] = {vv.x, vv.y, vv.z, vv.w};
#pragma unroll
            for (int i = 0; i < 4; i++) {
                float hf = rndtf32(vva[i]);
                V2[r*68 + d0 + i] = make_float2(hf, vva[i] - hf);
            }
        }
        __syncthreads();

        if (ktile + 1 < S_/64) prefetch_raw(ktile + 1);

        float sacc[8][4];
#pragma unroll
        for (int nt = 0; nt < 8; nt++)
#pragma unroll
            for (int j = 0; j < 4; j++) sacc[nt][j] = 0.f;

#pragma unroll
        for (int kt = 0; kt < 8; kt++) {
            int d0 = kt*8 + fc, d1 = d0 + 4;
            int s0 = (d0 >> 2) & 15, s1 = (d1 >> 2) & 15;
#pragma unroll
            for (int ntg = 0; ntg < 8; ntg += 4) {
                unsigned Bh0[4], Bl0[4], Bh1[4], Bl1[4];
#pragma unroll
                for (int j = 0; j < 4; j++) {
                    int nt = ntg + j;
                    float2 b0 = KT2[d0*68 + ((nt*8 + fr) ^ s0)];
                    float2 b1 = KT2[d1*68 + ((nt*8 + fr) ^ s1)];
                    Bh0[j] = __float_as_uint(b0.x); Bl0[j] = __float_as_uint(b0.y);
                    Bh1[j] = __float_as_uint(b1.x); Bl1[j] = __float_as_uint(b1.y);
                }
#pragma unroll
                for (int j = 0; j < 4; j++)
                    MMA_TF32(sacc[ntg+j], qh[kt][0],qh[kt][1],qh[kt][2],qh[kt][3],
                             Bl0[j], Bl1[j]);
#pragma unroll
                for (int j = 0; j < 4; j++)
                    MMA_TF32(sacc[ntg+j], ql[kt][0],ql[kt][1],ql[kt][2],ql[kt][3],
                             Bh0[j], Bh1[j]);
#pragma unroll
                for (int j = 0; j < 4; j++)
                    MMA_TF32(sacc[ntg+j], qh[kt][0],qh[kt][1],qh[kt][2],qh[kt][3],
                             Bh0[j], Bh1[j]);
            }
        }

        float rm0 = -1e30f, rm1 = -1e30f;
#pragma unroll
        for (int nt = 0; nt < 8; nt++) {
            rm0 = fmaxf(rm0, fmaxf(sacc[nt][0], sacc[nt][1]));
            rm1 = fmaxf(rm1, fmaxf(sacc[nt][2], sacc[nt][3]));
        }
        rm0 = fmaxf(rm0, __shfl_xor_sync(~0u, rm0, 1));
        rm0 = fmaxf(rm0, __shfl_xor_sync(~0u, rm0, 2));
        rm1 = fmaxf(rm1, __shfl_xor_sync(~0u, rm1, 1));
        rm1 = fmaxf(rm1, __shfl_xor_sync(~0u, rm1, 2));
        float mn0 = fmaxf(m0, rm0), mn1 = fmaxf(m1, rm1);
        float a0 = __expf(m0 - mn0), a1 = __expf(m1 - mn1);
        float sum0 = 0.f, sum1 = 0.f;
#pragma unroll
        for (int nt = 0; nt < 8; nt++) {
            sacc[nt][0] = __expf(sacc[nt][0] - mn0);
            sacc[nt][1] = __expf(sacc[nt][1] - mn0);
            sacc[nt][2] = __expf(sacc[nt][2] - mn1);
            sacc[nt][3] = __expf(sacc[nt][3] - mn1);
            sum0 += sacc[nt][0] + sacc[nt][1];
            sum1 += sacc[nt][2] + sacc[nt][3];
        }
        sum0 += __shfl_xor_sync(~0u, sum0, 1);
        sum0 += __shfl_xor_sync(~0u, sum0, 2);
        sum1 += __shfl_xor_sync(~0u, sum1, 1);
        sum1 += __shfl_xor_sync(~0u, sum1, 2);
        m0 = mn0; m1 = mn1;
        l0 = l0*a0 + sum0;
        l1 = l1*a1 + sum1;
#pragma unroll
        for (int nt = 0; nt < 8; nt++) {
            oacc[nt][0] *= a0; oacc[nt][1] *= a0;
            oacc[nt][2] *= a1; oacc[nt][3] *= a1;
        }

        __syncthreads();

#pragma unroll
        for (int nt = 0; nt < 8; nt++) {
#pragma unroll
            for (int j = 0; j < 4; j++) {
                int row = w16 + fr + (j >> 1)*8;
                int col = nt*8 + 2*fc + (j & 1);
                float p = sacc[nt][j];
                float hf = rndtf32(p);
                KT2[row*68 + col] = make_float2(hf, p - hf);
            }
        }
        __syncthreads();

#pragma unroll
        for (int kt = 0; kt < 8; kt++) {
            float2 A0 = KT2[(w16+fr  )*68 + kt*8 + fc    ];
            float2 A1 = KT2[(w16+fr+8)*68 + kt*8 + fc    ];
            float2 A2 = KT2[(w16+fr  )*68 + kt*8 + fc + 4];
            float2 A3 = KT2[(w16+fr+8)*68 + kt*8 + fc + 4];
            unsigned ph[4] = {__float_as_uint(A0.x), __float_as_uint(A1.x),
                              __float_as_uint(A2.x), __float_as_uint(A3.x)};
            unsigned pl[4] = {__float_as_uint(A0.y), __float_as_uint(A1.y),
                              __float_as_uint(A2.y), __float_as_uint(A3.y)};
#pragma unroll
            for (int ntg = 0; ntg < 8; ntg += 4) {
                unsigned Bh0[4], Bl0[4], Bh1[4], Bl1[4];
#pragma unroll
                for (int j = 0; j < 4; j++) {
                    int nt = ntg + j;
                    float2 b0 = V2[(kt*8 + fc    )*68 + nt*8 + fr];
                    float2 b1 = V2[(kt*8 + fc + 4)*68 + nt*8 + fr];
                    Bh0[j] = __float_as_uint(b0.x); Bl0[j] = __float_as_uint(b0.y);
                    Bh1[j] = __float_as_uint(b1.x); Bl1[j] = __float_as_uint(b1.y);
                }
#pragma unroll
                for (int j = 0; j < 4; j++)
                    MMA_TF32(oacc[ntg+j], ph[0],ph[1],ph[2],ph[3], Bl0[j], Bl1[j]);
#pragma unroll
                for (int j = 0; j < 4; j++)
                    MMA_TF32(oacc[ntg+j], pl[0],pl[1],pl[2],pl[3], Bh0[j], Bh1[j]);
#pragma unroll
                for (int j = 0; j < 4; j++)
                    MMA_TF32(oacc[ntg+j], ph[0],ph[1],ph[2],ph[3], Bh0[j], Bh1[j]);
            }
        }
    }

    // ---- finalize: write hi/lo split planes ----
    float inv0 = 1.f / l0, inv1 = 1.f / l1;
    int tok0 = b*S_ + qt*64 + w16 + fr;
#pragma unroll
    for (int nt = 0; nt < 8; nt++) {
        int col = h*DH_ + nt*8 + 2*fc;
        float v00 = oacc[nt][0]*inv0, v01 = oacc[nt][1]*inv0;
        float v10 = oacc[nt][2]*inv1, v11 = oacc[nt][3]*inv1;
        float h00 = rndtf32(v00), h01 = rndtf32(v01);
        float h10 = rndtf32(v10), h11 = rndtf32(v11);
        size_t off0 = (size_t)tok0*D_ + col;
        size_t off1 = (size_t)(tok0+8)*D_ + col;
        *(float2*)(oh + off0) = make_float2(h00, h01);
        *(float2*)(ol + off0) = make_float2(rndtf32(v00 - h00), rndtf32(v01 - h01));
        *(float2*)(oh + off1) = make_float2(h10, h11);
        *(float2*)(ol + off1) = make_float2(rndtf32(v10 - h10), rndtf32(v11 - h11));
    }
}

// ---------------------------------------------------------------- combine
__global__ void combine_kernel(const float* __restrict__ x1,
                               float* __restrict__ out)
{
    size_t idx = ((size_t)blockIdx.x * 256 + threadIdx.x) * 4;
    if (idx >= (size_t)T_*D_) return;
    int t = (int)(idx >> 10);
    int c = (int)(idx & (D_-1));
    float w0 = g_tokW[2*t], w1 = g_tokW[2*t+1];
    float4 a  = *(const float4*)(x1 + idx);
    float4 y0 = *(const float4*)(g_ybuf + (size_t)(2*t)*D_ + c);
    float4 y1 = *(const float4*)(g_ybuf + (size_t)(2*t+1)*D_ + c);
    float4 r;
    r.x = a.x + w0*y0.x + w1*y1.x;
    r.y = a.y + w0*y0.y + w1*y1.y;
    r.z = a.z + w0*y0.z + w1*y1.z;
    r.w = a.w + w0*y0.w + w1*y1.w;
    *(float4*)(out + idx) = r;
}

// ---------------------------------------------------------------- launch
extern "C" void kernel_launch(void* const* d_in, const int* in_sizes, int n_in,
                              void* d_out, int out_size)
{
    const float* x      = (const float*)d_in[0];
    const float* ln1_g  = (const float*)d_in[1];
    const float* ln1_b  = (const float*)d_in[2];
    const float* ln2_g  = (const float*)d_in[3];
    const float* ln2_b  = (const float*)d_in[4];
    const float* w_qkv  = (const float*)d_in[5];
    const float* b_qkv  = (const float*)d_in[6];
    const float* w_out  = (const float*)d_in[7];
    const float* b_out  = (const float*)d_in[8];
    const float* w_gate = (const float*)d_in[9];
    const float* w1     = (const float*)d_in[10];
    const float* b1     = (const float*)d_in[11];
    const float* w2     = (const float*)d_in[12];
    const float* b2     = (const float*)d_in[13];
    float* out = (float*)d_out;

    float *p_hh, *p_hl, *p_qkv, *p_ah, *p_al, *p_x1, *p_moeinR, *p_he, *p_ybuf;
    int *p_exTok, *p_exDst, *p_cnt;
    cudaGetSymbolAddress((void**)&p_hh,     g_hh);
    cudaGetSymbolAddress((void**)&p_hl,     g_hl);
    cudaGetSymbolAddress((void**)&p_qkv,    g_qkv);
    cudaGetSymbolAddress((void**)&p_ah,     g_ah);
    cudaGetSymbolAddress((void**)&p_al,     g_al);
    cudaGetSymbolAddress((void**)&p_x1,     g_x1);
    cudaGetSymbolAddress((void**)&p_moeinR, g_moeinR);
    cudaGetSymbolAddress((void**)&p_he,     g_he);
    cudaGetSymbolAddress((void**)&p_ybuf,   g_ybuf);
    cudaGetSymbolAddress((void**)&p_exTok,  g_exTok);
    cudaGetSymbolAddress((void**)&p_exDst,  g_exDst);
    cudaGetSymbolAddress((void**)&p_cnt,    g_cnt);

    cudaFuncSetAttribute(moe_mma_kernel<true>,
        cudaFuncAttributeMaxDynamicSharedMemorySize, DSMEM_BYTES);
    cudaFuncSetAttribute(moe_mma_kernel<false>,
        cudaFuncAttributeMaxDynamicSharedMemorySize, DSMEM_BYTES);
    cudaFuncSetAttribute(mma3_kernel<false>,
        cudaFuncAttributeMaxDynamicSharedMemorySize, MMA3_SMEM);
    cudaFuncSetAttribute(mma3_kernel<true>,
        cudaFuncAttributeMaxDynamicSharedMemorySize, MMA3_SMEM);
    cudaFuncSetAttribute(attn_mma_kernel,
        cudaFuncAttributeMaxDynamicSharedMemorySize, ATTN_SMEM);

    zero_cnt_kernel<<<1, 32>>>();

    // LN1 -> hi/lo split planes
    ln_split_kernel<<<T_, 256>>>(x, ln1_g, ln1_b, p_hh, p_hl);

    // QKV (3xTF32, fp32-grade)
    mma3_kernel<false><<<dim3(3*D_/128, T_/128, 1), 256, MMA3_SMEM>>>(
        p_hh, p_hl, w_qkv, b_qkv, nullptr, p_qkv, 3*D_, D_);

    // attention (tf32x3 flash); writes hi/lo split output
    attn_mma_kernel<<<dim3(S_/64, H_, B_), 128, ATTN_SMEM>>>(p_qkv, p_ah, p_al);

    // out-proj + residual (3xTF32)
    mma3_kernel<true><<<dim3(D_/128, T_/128, 1), 256, MMA3_SMEM>>>(
        p_ah, p_al, w_out, b_out, x, p_x1, D_, D_);

    // LN2 + gate + routing fused; writes only rounded plane for GEMM1
    ln2_gate_kernel<<<T_, 256>>>(p_x1, ln2_g, ln2_b, w_gate, p_moeinR);

    // expert GEMM1: he = rnd(gelu(moeinR @ rnd(w1) + b1))
    moe_mma_kernel<true><<<dim3(DFF_/128, T_/128, E_), 256, DSMEM_BYTES>>>(
        p_moeinR, w1, b1, p_he,
        DFF_, D_, p_exTok, p_exDst, p_cnt,
        (size_t)D_*DFF_, DFF_, T_);

    // expert GEMM2: ybuf = he @ rnd(w2) + b2
    moe_mma_kernel<false><<<dim3(D_/128, T_/128, E_), 256, DSMEM_BYTES>>>(
        p_he, w2, b2, p_ybuf,
        D_, DFF_, p_exDst, p_exDst, p_cnt,
        (size_t)DFF_*D_, D_, T_);

    // combine: out = x1 + w0*y0 + w1*y1
    combine_kernel<<<(T_*D_/4 + 255)/256, 256>>>(p_x1, out);
}

// round 16
// speedup vs baseline: 1.0379x; 1.0379x over previous
#include <cuda_runtime.h>
#include <math.h>

#define B_ 4
#define S_ 2048
#define D_ 1024
#define H_ 16
#define DH_ 64
#define E_ 8
#define DFF_ 4096
#define T_ (B_*S_)          // 8192 tokens

// ---------------- scratch (device globals; no cudaMalloc allowed) ----------
__device__ float g_hh[(size_t)T_*D_];           // LN1 out, tf32 hi plane
__device__ float g_hl[(size_t)T_*D_];           // LN1 out, tf32 lo plane
__device__ float g_qkv[(size_t)T_*3*D_];        // qkv
__device__ float g_ah[(size_t)T_*D_];           // attention out, hi plane
__device__ float g_al[(size_t)T_*D_];           // attention out, lo plane
__device__ float g_x1[(size_t)T_*D_];           // post-attn residual
__device__ float g_moein[(size_t)T_*D_];        // LN2 out, fp32 (gate input)
__device__ float g_moeinR[(size_t)T_*D_];       // LN2 out, RNA tf32 (GEMM1 A)
__device__ float g_he[(size_t)2*T_*DFF_];       // expert hidden (rounded)
__device__ float g_ybuf[(size_t)2*T_*D_];       // expert out
__device__ int   g_cnt[E_];
__device__ int   g_exTok[E_*T_];
__device__ int   g_exDst[E_*T_];
__device__ float g_tokW[2*T_];

// smem geometry
#define AS_SZ (128*36)
#define BS_SZ (32*136)
#define STG_SZ (AS_SZ + BS_SZ)
#define DSMEM_BYTES (2*STG_SZ*4)            // 71680 B (MoE, 2-stage)
#define STG3_SZ (2*AS_SZ + BS_SZ)
#define MMA3_SMEM (2*STG3_SZ*4)             // 108544 B (2 CTAs/SM)
#define ATTN_SMEM (2*64*68*8 + 8192*4)      // 102400 B (2 CTAs/SM)

__device__ __forceinline__ unsigned f2tf32(float x) {
    unsigned r;
    asm("cvt.rna.tf32.f32 %0, %1;" : "=r"(r) : "f"(x));
    return r;
}
__device__ __forceinline__ float rndtf32(float x) {
    return __uint_as_float(f2tf32(x));
}
__device__ __forceinline__ float gelu_fast(float u) {
    // gelu tanh-approx with fast tanh: tanh(t) = sign(t)*(1-e)/(1+e), e = exp(-2|t|)
    float t = 0.7978845608028654f*(u + 0.044715f*u*u*u);
    float a = fabsf(t);
    float e = __expf(-2.f*a);
    float th = __fdividef(1.f - e, 1.f + e);
    th = copysignf(th, t);
    return 0.5f*u*(1.f + th);
}
__device__ __forceinline__ void cpasync16(float* dst, const float* src, bool pred) {
    unsigned d = (unsigned)__cvta_generic_to_shared(dst);
    int sz = pred ? 16 : 0;
    asm volatile("cp.async.cg.shared.global [%0], [%1], 16, %2;\n"
                 :: "r"(d), "l"(src), "r"(sz));
}
#define MMA_TF32(c, a0,a1,a2,a3, b0,b1)                                     \
    asm volatile(                                                           \
        "mma.sync.aligned.m16n8k8.row.col.f32.tf32.tf32.f32 "               \
        "{%0,%1,%2,%3}, {%4,%5,%6,%7}, {%8,%9}, {%0,%1,%2,%3};\n"           \
        : "+f"((c)[0]), "+f"((c)[1]), "+f"((c)[2]), "+f"((c)[3])            \
        : "r"(a0), "r"(a1), "r"(a2), "r"(a3), "r"(b0), "r"(b1))

// ---------------------------------------------------------------- zero cnt
__global__ void zero_cnt_kernel() {
    if (threadIdx.x < E_) g_cnt[threadIdx.x] = 0;
}

// ---------------------------------------------------------------- layernorm (fp32 + rounded planes)
__global__ void ln2_fused_kernel(const float* __restrict__ x,
                                 const float* __restrict__ g,
                                 const float* __restrict__ b,
                                 float* __restrict__ out,
                                 float* __restrict__ outR) {
    int row = blockIdx.x;
    int t = threadIdx.x;
    const float* xr = x + (size_t)row * D_;
    float4 v = *(const float4*)(xr + t*4);
    float s = v.x + v.y + v.z + v.w;
    float ss = v.x*v.x + v.y*v.y + v.z*v.z + v.w*v.w;
#pragma unroll
    for (int m = 16; m; m >>= 1) {
        s  += __shfl_xor_sync(~0u, s, m);
        ss += __shfl_xor_sync(~0u, ss, m);
    }
    __shared__ float rs[8], rss[8];
    if ((t & 31) == 0) { rs[t>>5] = s; rss[t>>5] = ss; }
    __syncthreads();
    float sum = 0.f, sumsq = 0.f;
#pragma unroll
    for (int i = 0; i < 8; i++) { sum += rs[i]; sumsq += rss[i]; }
    float mean = sum * (1.f/D_);
    float var  = sumsq * (1.f/D_) - mean*mean;
    float rstd = rsqrtf(var + 1e-5f);
    float4 gv = *(const float4*)(g + t*4);
    float4 bv = *(const float4*)(b + t*4);
    float4 o, oR;
    o.x = (v.x-mean)*rstd*gv.x + bv.x;  oR.x = rndtf32(o.x);
    o.y = (v.y-mean)*rstd*gv.y + bv.y;  oR.y = rndtf32(o.y);
    o.z = (v.z-mean)*rstd*gv.z + bv.z;  oR.z = rndtf32(o.z);
    o.w = (v.w-mean)*rstd*gv.w + bv.w;  oR.w = rndtf32(o.w);
    *(float4*)(out  + (size_t)row * D_ + t*4) = o;
    *(float4*)(outR + (size_t)row * D_ + t*4) = oR;
}

// ---------------------------------------------------------------- layernorm (hi/lo split out)
__global__ void ln_split_kernel(const float* __restrict__ x,
                                const float* __restrict__ g,
                                const float* __restrict__ b,
                                float* __restrict__ outh,
                                float* __restrict__ outl) {
    int row = blockIdx.x;
    int t = threadIdx.x;
    const float* xr = x + (size_t)row * D_;
    float4 v = *(const float4*)(xr + t*4);
    float s = v.x + v.y + v.z + v.w;
    float ss = v.x*v.x + v.y*v.y + v.z*v.z + v.w*v.w;
#pragma unroll
    for (int m = 16; m; m >>= 1) {
        s  += __shfl_xor_sync(~0u, s, m);
        ss += __shfl_xor_sync(~0u, ss, m);
    }
    __shared__ float rs[8], rss[8];
    if ((t & 31) == 0) { rs[t>>5] = s; rss[t>>5] = ss; }
    __syncthreads();
    float sum = 0.f, sumsq = 0.f;
#pragma unroll
    for (int i = 0; i < 8; i++) { sum += rs[i]; sumsq += rss[i]; }
    float mean = sum * (1.f/D_);
    float var  = sumsq * (1.f/D_) - mean*mean;
    float rstd = rsqrtf(var + 1e-5f);
    float4 gv = *(const float4*)(g + t*4);
    float4 bv = *(const float4*)(b + t*4);
    float vv[4] = {v.x, v.y, v.z, v.w};
    float gg[4] = {gv.x, gv.y, gv.z, gv.w};
    float bb[4] = {bv.x, bv.y, bv.z, bv.w};
    float4 oh, ol;
    float* ohp = &oh.x; float* olp = &ol.x;
#pragma unroll
    for (int i = 0; i < 4; i++) {
        float h = (vv[i]-mean)*rstd*gg[i] + bb[i];
        float hf = rndtf32(h);
        ohp[i] = hf;
        olp[i] = rndtf32(h - hf);
    }
    *(float4*)(outh + (size_t)row * D_ + t*4) = oh;
    *(float4*)(outl + (size_t)row * D_ + t*4) = ol;
}

// ---------------------------------------------------------------- MoE mma (2-stage)
template<bool GELU>
__global__ void __launch_bounds__(256, 2)
moe_mma_kernel(const float* __restrict__ A,
               const float* __restrict__ Bw,
               const float* __restrict__ bias,
               float* __restrict__ C,
               int N, int K,
               const int* __restrict__ gatherA,
               const int* __restrict__ scatterC,
               const int* __restrict__ cnt,
               size_t bStride, int biasStride, int listStride)
{
    extern __shared__ float smem[];
    int e = blockIdx.z;
    int Me = cnt[e];
    int m0 = blockIdx.y * 128;
    if (m0 >= Me) return;
    int n0 = blockIdx.x * 128;

    const float* Bp    = Bw + (size_t)e * bStride;
    const float* biasp = bias + (size_t)e * biasStride;
    const int*   gA    = gatherA  + (size_t)e * listStride;
    const int*   sC    = scatterC + (size_t)e * listStride;

    int tid = threadIdx.x, lane = tid & 31, warp = tid >> 5;
    int wm = warp >> 2, wn = warp & 3;
    int fr = lane >> 2, fc = lane & 3;

    int aRowBase = tid >> 3;
    int aKq = (tid & 7) * 4;
    const float* aSrc[4]; bool aValid[4];
#pragma unroll
    for (int i = 0; i < 4; i++) {
        int r = aRowBase + i*32;
        int rowA = m0 + r;
        aValid[i] = rowA < Me;
        aSrc[i] = aValid[i] ? (A + (size_t)gA[rowA]*K + aKq) : A;
    }
    int bKBase = tid >> 5;
    int bn4 = (tid & 31) * 4;
    const float* bSrc[4];
#pragma unroll
    for (int i = 0; i < 4; i++)
        bSrc[i] = Bp + (size_t)(bKBase + i*8)*N + n0 + bn4;

    float acc[4][4][4];
#pragma unroll
    for (int mi = 0; mi < 4; mi++)
#pragma unroll
        for (int ni = 0; ni < 4; ni++)
#pragma unroll
            for (int j = 0; j < 4; j++) acc[mi][ni][j] = 0.f;

    int nk = K >> 5;

    auto prefetch = [&](int s, int kt) {
        float* As_ = smem + s*STG_SZ;
        float* Bs_ = As_ + AS_SZ;
#pragma unroll
        for (int i = 0; i < 4; i++)
            cpasync16(As_ + (aRowBase + i*32)*36 + aKq,
                      aSrc[i] + (size_t)kt*32, aValid[i]);
#pragma unroll
        for (int i = 0; i < 4; i++)
            cpasync16(Bs_ + (bKBase + i*8)*136 + bn4,
                      bSrc[i] + (size_t)kt*32*N, true);
        asm volatile("cp.async.commit_group;\n");
    };

    prefetch(0, 0);

    for (int kt = 0; kt < nk; kt++) {
        int s = kt & 1;
        bool more = (kt + 1) < nk;
        if (more) prefetch(s ^ 1, kt + 1);
        if (more) asm volatile("cp.async.wait_group 1;\n");
        else      asm volatile("cp.async.wait_group 0;\n");
        __syncthreads();

        const float* As_ = smem + s*STG_SZ;
        const float* Bs_ = As_ + AS_SZ;
#pragma unroll
        for (int kk8 = 0; kk8 < 4; kk8++) {
            int kk = kk8 * 8;
            unsigned af[4][4], bf[4][2];
#pragma unroll
            for (int mi = 0; mi < 4; mi++) {
                int mb = wm*64 + mi*16;
                af[mi][0] = __float_as_uint(As_[(mb + fr    )*36 + kk + fc    ]);
                af[mi][1] = __float_as_uint(As_[(mb + fr + 8)*36 + kk + fc    ]);
                af[mi][2] = __float_as_uint(As_[(mb + fr    )*36 + kk + fc + 4]);
                af[mi][3] = __float_as_uint(As_[(mb + fr + 8)*36 + kk + fc + 4]);
            }
#pragma unroll
            for (int ni = 0; ni < 4; ni++) {
                int cb = wn*32 + ni*8;
                bf[ni][0] = f2tf32(Bs_[(kk + fc    )*136 + cb + fr]);
                bf[ni][1] = f2tf32(Bs_[(kk + fc + 4)*136 + cb + fr]);
            }
#pragma unroll
            for (int mi = 0; mi < 4; mi++)
#pragma unroll
                for (int ni = 0; ni < 4; ni++)
                    MMA_TF32(acc[mi][ni], af[mi][0],af[mi][1],af[mi][2],af[mi][3],
                             bf[ni][0], bf[ni][1]);
        }
        __syncthreads();
    }

#pragma unroll
    for (int mi = 0; mi < 4; mi++) {
        int rbase = m0 + wm*64 + mi*16 + fr;
#pragma unroll
        for (int half = 0; half < 2; half++) {
            int m = rbase + half*8;
            if (m >= Me) continue;
            int crow = sC[m];
#pragma unroll
            for (int ni = 0; ni < 4; ni++) {
                int n = n0 + wn*32 + ni*8 + fc*2;
                float v0 = acc[mi][ni][half*2 + 0] + biasp[n];
                float v1 = acc[mi][ni][half*2 + 1] + biasp[n+1];
                if (GELU) {
                    v0 = rndtf32(gelu_fast(v0));
                    v1 = rndtf32(gelu_fast(v1));
                }
                *(float2*)(C + (size_t)crow * N + n) = make_float2(v0, v1);
            }
        }
    }
}

// ---------------------------------------------------------------- 3xTF32 dense GEMM (R10)
template<bool RES>
__global__ void __launch_bounds__(256, 2)
mma3_kernel(const float* __restrict__ Ah,
            const float* __restrict__ Al,
            const float* __restrict__ Bw,
            const float* __restrict__ bias,
            const float* __restrict__ res,
            float* __restrict__ C,
            int N, int K)
{
    extern __shared__ float smem[];
    int m0 = blockIdx.y * 128;
    int n0 = blockIdx.x * 128;

    int tid = threadIdx.x, lane = tid & 31, warp = tid >> 5;
    int wm = warp >> 2, wn = warp & 3;
    int fr = lane >> 2, fc = lane & 3;

    int aRowBase = tid >> 3;
    int aKq = (tid & 7) * 4;
    const float* ahSrc[4];
    const float* alSrc[4];
#pragma unroll
    for (int i = 0; i < 4; i++) {
        size_t off = (size_t)(m0 + aRowBase + i*32)*K + aKq;
        ahSrc[i] = Ah + off;
        alSrc[i] = Al + off;
    }
    int bKBase = tid >> 5;
    int bn4 = (tid & 31) * 4;
    const float* bSrc[4];
#pragma unroll
    for (int i = 0; i < 4; i++)
        bSrc[i] = Bw + (size_t)(bKBase + i*8)*N + n0 + bn4;

    float acc[4][4][4];
#pragma unroll
    for (int mi = 0; mi < 4; mi++)
#pragma unroll
        for (int ni = 0; ni < 4; ni++)
#pragma unroll
            for (int j = 0; j < 4; j++) acc[mi][ni][j] = 0.f;

    int nk = K >> 5;

    auto prefetch = [&](int s, int kt) {
        float* Ah_ = smem + s*STG3_SZ;
        float* Al_ = Ah_ + AS_SZ;
        float* Bs_ = Al_ + AS_SZ;
#pragma unroll
        for (int i = 0; i < 4; i++) {
            int off = (aRowBase + i*32)*36 + aKq;
            cpasync16(Ah_ + off, ahSrc[i] + (size_t)kt*32, true);
            cpasync16(Al_ + off, alSrc[i] + (size_t)kt*32, true);
        }
#pragma unroll
        for (int i = 0; i < 4; i++)
            cpasync16(Bs_ + (bKBase + i*8)*136 + bn4,
                      bSrc[i] + (size_t)kt*32*N, true);
        asm volatile("cp.async.commit_group;\n");
    };

    prefetch(0, 0);

    for (int kt = 0; kt < nk; kt++) {
        int s = kt & 1;
        bool more = (kt + 1) < nk;
        if (more) prefetch(s ^ 1, kt + 1);
        if (more) asm volatile("cp.async.wait_group 1;\n");
        else      asm volatile("cp.async.wait_group 0;\n");
        __syncthreads();

        const float* Ah_ = smem + s*STG3_SZ;
        const float* Al_ = Ah_ + AS_SZ;
        const float* Bs_ = Al_ + AS_SZ;
#pragma unroll
        for (int kk8 = 0; kk8 < 4; kk8++) {
            int kk = kk8 * 8;
            unsigned ah[4][4], al[4][4], bh[4][2], bl[4][2];
#pragma unroll
            for (int mi = 0; mi < 4; mi++) {
                int mb = wm*64 + mi*16;
                int o0 = (mb + fr    )*36 + kk + fc;
                int o1 = (mb + fr + 8)*36 + kk + fc;
                ah[mi][0] = __float_as_uint(Ah_[o0]);
                ah[mi][1] = __float_as_uint(Ah_[o1]);
                ah[mi][2] = __float_as_uint(Ah_[o0 + 4]);
                ah[mi][3] = __float_as_uint(Ah_[o1 + 4]);
                al[mi][0] = __float_as_uint(Al_[o0]);
                al[mi][1] = __float_as_uint(Al_[o1]);
                al[mi][2] = __float_as_uint(Al_[o0 + 4]);
                al[mi][3] = __float_as_uint(Al_[o1 + 4]);
            }
#pragma unroll
            for (int ni = 0; ni < 4; ni++) {
                int cb = wn*32 + ni*8;
                float u0 = Bs_[(kk + fc    )*136 + cb + fr];
                float u1 = Bs_[(kk + fc + 4)*136 + cb + fr];
                bh[ni][0] = f2tf32(u0); bl[ni][0] = f2tf32(u0 - __uint_as_float(bh[ni][0]));
                bh[ni][1] = f2tf32(u1); bl[ni][1] = f2tf32(u1 - __uint_as_float(bh[ni][1]));
            }
            // pass 1: hi*lo
#pragma unroll
            for (int mi = 0; mi < 4; mi++)
#pragma unroll
                for (int ni = 0; ni < 4; ni++)
                    MMA_TF32(acc[mi][ni], ah[mi][0],ah[mi][1],ah[mi][2],ah[mi][3],
                             bl[ni][0], bl[ni][1]);
            // pass 2: lo*hi
#pragma unroll
            for (int mi = 0; mi < 4; mi++)
#pragma unroll
                for (int ni = 0; ni < 4; ni++)
                    MMA_TF32(acc[mi][ni], al[mi][0],al[mi][1],al[mi][2],al[mi][3],
                             bh[ni][0], bh[ni][1]);
            // pass 3: hi*hi
#pragma unroll
            for (int mi = 0; mi < 4; mi++)
#pragma unroll
                for (int ni = 0; ni < 4; ni++)
                    MMA_TF32(acc[mi][ni], ah[mi][0],ah[mi][1],ah[mi][2],ah[mi][3],
                             bh[ni][0], bh[ni][1]);
        }
        __syncthreads();
    }

#pragma unroll
    for (int mi = 0; mi < 4; mi++) {
        int rbase = m0 + wm*64 + mi*16 + fr;
#pragma unroll
        for (int half = 0; half < 2; half++) {
            int m = rbase + half*8;
#pragma unroll
            for (int ni = 0; ni < 4; ni++) {
                int n = n0 + wn*32 + ni*8 + fc*2;
                float v0 = acc[mi][ni][half*2 + 0] + bias[n];
                float v1 = acc[mi][ni][half*2 + 1] + bias[n+1];
                if (RES) {
                    v0 += res[(size_t)m * N + n];
                    v1 += res[(size_t)m * N + n + 1];
                }
                *(float2*)(C + (size_t)m * N + n) = make_float2(v0, v1);
            }
        }
    }
}

// ---------------------------------------------------------------- attention (tf32x3 flash, R10)
__global__ void __launch_bounds__(128, 2)
attn_mma_kernel(const float* __restrict__ qkv,
                float* __restrict__ oh, float* __restrict__ ol)
{
    extern __shared__ float2 sm2[];
    float2* KT2 = sm2;
    float2* V2  = sm2 + 64*68;
    float*  raw = (float*)(sm2 + 2*64*68);

    int qt = blockIdx.x, h = blockIdx.y, b = blockIdx.z;
    int tid = threadIdx.x;
    int lane = tid & 31, warp = tid >> 5;
    int fr = lane >> 2, fc = lane & 3;
    int w16 = warp * 16;
    size_t base = (size_t)b * S_ * (3*D_) + h*DH_;

    auto prefetch_raw = [&](int kt) {
#pragma unroll
        for (int rep = 0; rep < 8; rep++) {
            int c = rep*128 + tid;
            int r = c >> 4, off = (c & 15) * 4;
            const float* src = qkv + base + (size_t)(kt*64 + r)*(3*D_) + D_ + off;
            cpasync16(raw + r*64 + off, src, true);
        }
#pragma unroll
        for (int rep = 0; rep < 8; rep++) {
            int c = rep*128 + tid;
            int r = c >> 4, off = (c & 15) * 4;
            const float* src = qkv + base + (size_t)(kt*64 + r)*(3*D_) + 2*D_ + off;
            cpasync16(raw + 4096 + r*64 + off, src, true);
        }
        asm volatile("cp.async.commit_group;\n");
    };
    prefetch_raw(0);

    float* Qs = (float*)V2;
#pragma unroll
    for (int rep = 0; rep < 8; rep++) {
        int lin = rep*512 + tid*4;
        int r = lin >> 6, d0 = lin & 63;
        float4 q = *(const float4*)(qkv + base + (size_t)(qt*64 + r)*(3*D_) + d0);
        Qs[r*68 + d0 + 0] = q.x * 0.125f;
        Qs[r*68 + d0 + 1] = q.y * 0.125f;
        Qs[r*68 + d0 + 2] = q.z * 0.125f;
        Qs[r*68 + d0 + 3] = q.w * 0.125f;
    }
    __syncthreads();

    unsigned qh[8][4], ql[8][4];
#pragma unroll
    for (int kt = 0; kt < 8; kt++) {
        int c0 = kt*8 + fc;
        float v[4];
        v[0] = Qs[(w16+fr  )*68 + c0];
        v[1] = Qs[(w16+fr+8)*68 + c0];
        v[2] = Qs[(w16+fr  )*68 + c0 + 4];
        v[3] = Qs[(w16+fr+8)*68 + c0 + 4];
#pragma unroll
        for (int j = 0; j < 4; j++) {
            qh[kt][j] = f2tf32(v[j]);
            ql[kt][j] = f2tf32(v[j] - __uint_as_float(qh[kt][j]));
        }
    }

    float m0 = -1e30f, m1 = -1e30f, l0 = 0.f, l1 = 0.f;
    float oacc[8][4];
#pragma unroll
    for (int nt = 0; nt < 8; nt++)
#pragma unroll
        for (int j = 0; j < 4; j++) oacc[nt][j] = 0.f;

    for (int ktile = 0; ktile < S_/64; ktile++) {
        asm volatile("cp.async.wait_group 0;\n");
        __syncthreads();

#pragma unroll
        for (int rep = 0; rep < 8; rep++) {
            int lin = rep*512 + tid*4;
            int r = lin >> 6, d0 = lin & 63;
            float4 kv = *(const float4*)(raw + r*64 + d0);
            float kva[4] = {kv.x, kv.y, kv.z, kv.w};
#pragma unroll
            for (int i = 0; i < 4; i++) {
                int d = d0 + i;
                float hf = rndtf32(kva[i]);
                int col = r ^ ((d >> 2) & 15);
                KT2[d*68 + col] = make_float2(hf, kva[i] - hf);
            }
            float4 vv = *(const float4*)(raw + 4096 + r*64 + d0);
            float vva[4] = {vv.x, vv.y, vv.z, vv.w};
#pragma unroll
            for (int i = 0; i < 4; i++) {
                float hf = rndtf32(vva[i]);
                V2[r*68 + d0 + i] = make_float2(hf, vva[i] - hf);
            }
        }
        __syncthreads();

        if (ktile + 1 < S_/64) prefetch_raw(ktile + 1);

        float sacc[8][4];
#pragma unroll
        for (int nt = 0; nt < 8; nt++)
#pragma unroll
            for (int j = 0; j < 4; j++) sacc[nt][j] = 0.f;

#pragma unroll
        for (int kt = 0; kt < 8; kt++) {
            int d0 = kt*8 + fc, d1 = d0 + 4;
            int s0 = (d0 >> 2) & 15, s1 = (d1 >> 2) & 15;
#pragma unroll
            for (int ntg = 0; ntg < 8; ntg += 4) {
                unsigned Bh0[4], Bl0[4], Bh1[4], Bl1[4];
#pragma unroll
                for (int j = 0; j < 4; j++) {
                    int nt = ntg + j;
                    float2 b0 = KT2[d0*68 + ((nt*8 + fr) ^ s0)];
                    float2 b1 = KT2[d1*68 + ((nt*8 + fr) ^ s1)];
                    Bh0[j] = __float_as_uint(b0.x); Bl0[j] = __float_as_uint(b0.y);
                    Bh1[j] = __float_as_uint(b1.x); Bl1[j] = __float_as_uint(b1.y);
                }
#pragma unroll
                for (int j = 0; j < 4; j++)
                    MMA_TF32(sacc[ntg+j], qh[kt][0],qh[kt][1],qh[kt][2],qh[kt][3],
                             Bl0[j], Bl1[j]);
#pragma unroll
                for (int j = 0; j < 4; j++)
                    MMA_TF32(sacc[ntg+j], ql[kt][0],ql[kt][1],ql[kt][2],ql[kt][3],
                             Bh0[j], Bh1[j]);
#pragma unroll
                for (int j = 0; j < 4; j++)
                    MMA_TF32(sacc[ntg+j], qh[kt][0],qh[kt][1],qh[kt][2],qh[kt][3],
                             Bh0[j], Bh1[j]);
            }
        }

        float rm0 = -1e30f, rm1 = -1e30f;
#pragma unroll
        for (int nt = 0; nt < 8; nt++) {
            rm0 = fmaxf(rm0, fmaxf(sacc[nt][0], sacc[nt][1]));
            rm1 = fmaxf(rm1, fmaxf(sacc[nt][2], sacc[nt][3]));
        }
        rm0 = fmaxf(rm0, __shfl_xor_sync(~0u, rm0, 1));
        rm0 = fmaxf(rm0, __shfl_xor_sync(~0u, rm0, 2));
        rm1 = fmaxf(rm1, __shfl_xor_sync(~0u, rm1, 1));
        rm1 = fmaxf(rm1, __shfl_xor_sync(~0u, rm1, 2));
        float mn0 = fmaxf(m0, rm0), mn1 = fmaxf(m1, rm1);
        float a0 = __expf(m0 - mn0), a1 = __expf(m1 - mn1);
        float sum0 = 0.f, sum1 = 0.f;
#pragma unroll
        for (int nt = 0; nt < 8; nt++) {
            sacc[nt][0] = __expf(sacc[nt][0] - mn0);
            sacc[nt][1] = __expf(sacc[nt][1] - mn0);
            sacc[nt][2] = __expf(sacc[nt][2] - mn1);
            sacc[nt][3] = __expf(sacc[nt][3] - mn1);
            sum0 += sacc[nt][0] + sacc[nt][1];
            sum1 += sacc[nt][2] + sacc[nt][3];
        }
        sum0 += __shfl_xor_sync(~0u, sum0, 1);
        sum0 += __shfl_xor_sync(~0u, sum0, 2);
        sum1 += __shfl_xor_sync(~0u, sum1, 1);
        sum1 += __shfl_xor_sync(~0u, sum1, 2);
        m0 = mn0; m1 = mn1;
        l0 = l0*a0 + sum0;
        l1 = l1*a1 + sum1;
#pragma unroll
        for (int nt = 0; nt < 8; nt++) {
            oacc[nt][0] *= a0; oacc[nt][1] *= a0;
            oacc[nt][2] *= a1; oacc[nt][3] *= a1;
        }

        __syncthreads();

#pragma unroll
        for (int nt = 0; nt < 8; nt++) {
#pragma unroll
            for (int j = 0; j < 4; j++) {
                int row = w16 + fr + (j >> 1)*8;
                int col = nt*8 + 2*fc + (j & 1);
                float p = sacc[nt][j];
                float hf = rndtf32(p);
                KT2[row*68 + col] = make_float2(hf, p - hf);
            }
        }
        __syncthreads();

#pragma unroll
        for (int kt = 0; kt < 8; kt++) {
            float2 A0 = KT2[(w16+fr  )*68 + kt*8 + fc    ];
            float2 A1 = KT2[(w16+fr+8)*68 + kt*8 + fc    ];
            float2 A2 = KT2[(w16+fr  )*68 + kt*8 + fc + 4];
            float2 A3 = KT2[(w16+fr+8)*68 + kt*8 + fc + 4];
            unsigned ph[4] = {__float_as_uint(A0.x), __float_as_uint(A1.x),
                              __float_as_uint(A2.x), __float_as_uint(A3.x)};
            unsigned pl[4] = {__float_as_uint(A0.y), __float_as_uint(A1.y),
                              __float_as_uint(A2.y), __float_as_uint(A3.y)};
#pragma unroll
            for (int ntg = 0; ntg < 8; ntg += 4) {
                unsigned Bh0[4], Bl0[4], Bh1[4], Bl1[4];
#pragma unroll
                for (int j = 0; j < 4; j++) {
                    int nt = ntg + j;
                    float2 b0 = V2[(kt*8 + fc    )*68 + nt*8 + fr];
                    float2 b1 = V2[(kt*8 + fc + 4)*68 + nt*8 + fr];
                    Bh0[j] = __float_as_uint(b0.x); Bl0[j] = __float_as_uint(b0.y);
                    Bh1[j] = __float_as_uint(b1.x); Bl1[j] = __float_as_uint(b1.y);
                }
#pragma unroll
                for (int j = 0; j < 4; j++)
                    MMA_TF32(oacc[ntg+j], ph[0],ph[1],ph[2],ph[3], Bl0[j], Bl1[j]);
#pragma unroll
                for (int j = 0; j < 4; j++)
                    MMA_TF32(oacc[ntg+j], pl[0],pl[1],pl[2],pl[3], Bh0[j], Bh1[j]);
#pragma unroll
                for (int j = 0; j < 4; j++)
                    MMA_TF32(oacc[ntg+j], ph[0],ph[1],ph[2],ph[3], Bh0[j], Bh1[j]);
            }
        }
    }

    // ---- finalize: write hi/lo split planes ----
    float inv0 = 1.f / l0, inv1 = 1.f / l1;
    int tok0 = b*S_ + qt*64 + w16 + fr;
#pragma unroll
    for (int nt = 0; nt < 8; nt++) {
        int col = h*DH_ + nt*8 + 2*fc;
        float v00 = oacc[nt][0]*inv0, v01 = oacc[nt][1]*inv0;
        float v10 = oacc[nt][2]*inv1, v11 = oacc[nt][3]*inv1;
        float h00 = rndtf32(v00), h01 = rndtf32(v01);
        float h10 = rndtf32(v10), h11 = rndtf32(v11);
        size_t off0 = (size_t)tok0*D_ + col;
        size_t off1 = (size_t)(tok0+8)*D_ + col;
        *(float2*)(oh + off0) = make_float2(h00, h01);
        *(float2*)(ol + off0) = make_float2(rndtf32(v00 - h00), rndtf32(v01 - h01));
        *(float2*)(oh + off1) = make_float2(h10, h11);
        *(float2*)(ol + off1) = make_float2(rndtf32(v10 - h10), rndtf32(v11 - h11));
    }
}

// ---------------------------------------------------------------- gate/top2
__global__ void gate_kernel(const float* __restrict__ xin,
                            const float* __restrict__ wg)
{
    int t = blockIdx.x;
    int tid = threadIdx.x;
    const float* xr = xin + (size_t)t * D_;
    float acc[E_] = {};
    for (int d = tid; d < D_; d += 128) {
        float xv = xr[d];
        const float* w = wg + d*E_;
#pragma unroll
        for (int e = 0; e < E_; e++) acc[e] = fmaf(xv, w[e], acc[e]);
    }
#pragma unroll
    for (int e = 0; e < E_; e++)
#pragma unroll
        for (int msk = 16; msk; msk >>= 1)
            acc[e] += __shfl_xor_sync(~0u, acc[e], msk);
    __shared__ float red[4][E_];
    if ((tid & 31) == 0)
#pragma unroll
        for (int e = 0; e < E_; e++) red[tid>>5][e] = acc[e];
    __syncthreads();
    if (tid == 0) {
        float lg[E_];
#pragma unroll
        for (int e = 0; e < E_; e++)
            lg[e] = red[0][e] + red[1][e] + red[2][e] + red[3][e];
        int i0 = 0;
#pragma unroll
        for (int e = 1; e < E_; e++) if (lg[e] > lg[i0]) i0 = e;
        int i1 = -1;
#pragma unroll
        for (int e = 0; e < E_; e++)
            if (e != i0 && (i1 < 0 || lg[e] > lg[i1])) i1 = e;
        float d10 = __expf(lg[i1] - lg[i0]);
        float w0 = 1.f / (1.f + d10);
        float w1 = d10 * w0;
        g_tokW[2*t]   = w0;
        g_tokW[2*t+1] = w1;
        int p0 = atomicAdd(&g_cnt[i0], 1);
        g_exTok[i0*T_ + p0] = t;  g_exDst[i0*T_ + p0] = 2*t;
        int p1 = atomicAdd(&g_cnt[i1], 1);
        g_exTok[i1*T_ + p1] = t;  g_exDst[i1*T_ + p1] = 2*t+1;
    }
}

// ---------------------------------------------------------------- combine
__global__ void combine_kernel(const float* __restrict__ x1,
                               float* __restrict__ out)
{
    size_t idx = ((size_t)blockIdx.x * 256 + threadIdx.x) * 4;
    if (idx >= (size_t)T_*D_) return;
    int t = (int)(idx >> 10);
    int c = (int)(idx & (D_-1));
    float w0 = g_tokW[2*t], w1 = g_tokW[2*t+1];
    float4 a  = *(const float4*)(x1 + idx);
    float4 y0 = *(const float4*)(g_ybuf + (size_t)(2*t)*D_ + c);
    float4 y1 = *(const float4*)(g_ybuf + (size_t)(2*t+1)*D_ + c);
    float4 r;
    r.x = a.x + w0*y0.x + w1*y1.x;
    r.y = a.y + w0*y0.y + w1*y1.y;
    r.z = a.z + w0*y0.z + w1*y1.z;
    r.w = a.w + w0*y0.w + w1*y1.w;
    *(float4*)(out + idx) = r;
}

// ---------------------------------------------------------------- launch
extern "C" void kernel_launch(void* const* d_in, const int* in_sizes, int n_in,
                              void* d_out, int out_size)
{
    const float* x      = (const float*)d_in[0];
    const float* ln1_g  = (const float*)d_in[1];
    const float* ln1_b  = (const float*)d_in[2];
    const float* ln2_g  = (const float*)d_in[3];
    const float* ln2_b  = (const float*)d_in[4];
    const float* w_qkv  = (const float*)d_in[5];
    const float* b_qkv  = (const float*)d_in[6];
    const float* w_out  = (const float*)d_in[7];
    const float* b_out  = (const float*)d_in[8];
    const float* w_gate = (const float*)d_in[9];
    const float* w1     = (const float*)d_in[10];
    const float* b1     = (const float*)d_in[11];
    const float* w2     = (const float*)d_in[12];
    const float* b2     = (const float*)d_in[13];
    float* out = (float*)d_out;

    float *p_hh, *p_hl, *p_qkv, *p_ah, *p_al, *p_x1, *p_moein, *p_moeinR, *p_he, *p_ybuf;
    int *p_exTok, *p_exDst, *p_cnt;
    cudaGetSymbolAddress((void**)&p_hh,     g_hh);
    cudaGetSymbolAddress((void**)&p_hl,     g_hl);
    cudaGetSymbolAddress((void**)&p_qkv,    g_qkv);
    cudaGetSymbolAddress((void**)&p_ah,     g_ah);
    cudaGetSymbolAddress((void**)&p_al,     g_al);
    cudaGetSymbolAddress((void**)&p_x1,     g_x1);
    cudaGetSymbolAddress((void**)&p_moein,  g_moein);
    cudaGetSymbolAddress((void**)&p_moeinR, g_moeinR);
    cudaGetSymbolAddress((void**)&p_he,     g_he);
    cudaGetSymbolAddress((void**)&p_ybuf,   g_ybuf);
    cudaGetSymbolAddress((void**)&p_exTok,  g_exTok);
    cudaGetSymbolAddress((void**)&p_exDst,  g_exDst);
    cudaGetSymbolAddress((void**)&p_cnt,    g_cnt);

    cudaFuncSetAttribute(moe_mma_kernel<true>,
        cudaFuncAttributeMaxDynamicSharedMemorySize, DSMEM_BYTES);
    cudaFuncSetAttribute(moe_mma_kernel<false>,
        cudaFuncAttributeMaxDynamicSharedMemorySize, DSMEM_BYTES);
    cudaFuncSetAttribute(mma3_kernel<false>,
        cudaFuncAttributeMaxDynamicSharedMemorySize, MMA3_SMEM);
    cudaFuncSetAttribute(mma3_kernel<true>,
        cudaFuncAttributeMaxDynamicSharedMemorySize, MMA3_SMEM);
    cudaFuncSetAttribute(attn_mma_kernel,
        cudaFuncAttributeMaxDynamicSharedMemorySize, ATTN_SMEM);

    zero_cnt_kernel<<<1, 32>>>();

    // LN1 -> hi/lo split planes
    ln_split_kernel<<<T_, 256>>>(x, ln1_g, ln1_b, p_hh, p_hl);

    // QKV (3xTF32, fp32-grade)
    mma3_kernel<false><<<dim3(3*D_/128, T_/128, 1), 256, MMA3_SMEM>>>(
        p_hh, p_hl, w_qkv, b_qkv, nullptr, p_qkv, 3*D_, D_);

    // attention (tf32x3 flash); writes hi/lo split output
    attn_mma_kernel<<<dim3(S_/64, H_, B_), 128, ATTN_SMEM>>>(p_qkv, p_ah, p_al);

    // out-proj + residual (3xTF32)
    mma3_kernel<true><<<dim3(D_/128, T_/128, 1), 256, MMA3_SMEM>>>(
        p_ah, p_al, w_out, b_out, x, p_x1, D_, D_);

    // LN2 -> fp32 plane (gate) + rounded plane (MoE A)
    ln2_fused_kernel<<<T_, 256>>>(p_x1, ln2_g, ln2_b, p_moein, p_moeinR);

    // gate + routing (fp32, reads unrounded moein) — standalone (R15 fusion regressed)
    gate_kernel<<<T_, 128>>>(p_moein, w_gate);

    // expert GEMM1: he = rnd(gelu_fast(moeinR @ rnd(w1) + b1))
    moe_mma_kernel<true><<<dim3(DFF_/128, T_/128, E_), 256, DSMEM_BYTES>>>(
        p_moeinR, w1, b1, p_he,
        DFF_, D_, p_exTok, p_exDst, p_cnt,
        (size_t)D_*DFF_, DFF_, T_);

    // expert GEMM2: ybuf = he @ rnd(w2) + b2
    moe_mma_kernel<false><<<dim3(D_/128, T_/128, E_), 256, DSMEM_BYTES>>>(
        p_he, w2, b2, p_ybuf,
        D_, DFF_, p_exDst, p_exDst, p_cnt,
        (size_t)DFF_*D_, D_, T_);

    // combine: out = x1 + w0*y0 + w1*y1
    combine_kernel<<<(T_*D_/4 + 255)/256, 256>>>(p_x1, out);
}